// round 1
// baseline (speedup 1.0000x reference)
#include <cuda_runtime.h>

// LuongAttention: O[b] = (Q Eᵀ) E  ==  Q (EᵀE).  Reassociate: G = EᵀE (128x128
// per batch), then O = Q G.  8x fewer FLOPs than the reference order, no giant
// intermediate.  All fp32.
//
// B=8, T=2048, D=128.

#define BB      8
#define TT      2048
#define DD      128
#define NSPLIT  16
#define KCHUNK  (TT / NSPLIT)        // 128

// Scratch (device globals — no allocation allowed in kernel_launch).
__device__ float g_part[BB * NSPLIT * DD * DD];  // 8 MB of partial EᵀE
__device__ float g_full[BB * DD * DD];           // 512 KB reduced G

// ---------------------------------------------------------------------------
// Kernel 1: partial G.  CTA (sp, b) computes sum over 128 k-rows of
// E[k][i]*E[k][j]  ->  g_part[b][sp][i][j].
// 256 threads, 8x8 register tile each (16x16 thread grid covers 128x128).
// ---------------------------------------------------------------------------
__global__ __launch_bounds__(256) void ete_partial(const float* __restrict__ enc) {
    extern __shared__ float s[];                 // [128][128] chunk, row = k
    const int tid = threadIdx.x;
    const int b = blockIdx.y, sp = blockIdx.x;

    const float4* src =
        (const float4*)(enc + (size_t)(b * NSPLIT + sp) * (KCHUNK * DD));
    float4* s4 = (float4*)s;
#pragma unroll
    for (int v = 0; v < 16; v++)                 // 4096 float4 / 256 threads
        s4[tid + v * 256] = src[tid + v * 256];
    __syncthreads();

    const int tx = tid & 15, ty = tid >> 4;
    const int i0 = ty * 8, j0 = tx * 8;

    float acc[8][8];
#pragma unroll
    for (int ii = 0; ii < 8; ii++)
#pragma unroll
        for (int jj = 0; jj < 8; jj++) acc[ii][jj] = 0.0f;

#pragma unroll 4
    for (int k = 0; k < 128; k++) {
        const float* row = s + k * 128;
        float a[8], bv[8];
        *(float4*)&a[0]  = *(const float4*)&row[i0];
        *(float4*)&a[4]  = *(const float4*)&row[i0 + 4];
        *(float4*)&bv[0] = *(const float4*)&row[j0];
        *(float4*)&bv[4] = *(const float4*)&row[j0 + 4];
#pragma unroll
        for (int ii = 0; ii < 8; ii++)
#pragma unroll
            for (int jj = 0; jj < 8; jj++)
                acc[ii][jj] = fmaf(a[ii], bv[jj], acc[ii][jj]);
    }

    float* outp = g_part + ((size_t)(b * NSPLIT + sp) << 14);
#pragma unroll
    for (int ii = 0; ii < 8; ii++) {
        float* r = outp + (i0 + ii) * 128 + j0;
        *(float4*)&r[0] = make_float4(acc[ii][0], acc[ii][1], acc[ii][2], acc[ii][3]);
        *(float4*)&r[4] = make_float4(acc[ii][4], acc[ii][5], acc[ii][6], acc[ii][7]);
    }
}

// ---------------------------------------------------------------------------
// Kernel 2: reduce partials.  g_full[b][r] = sum_s g_part[b][s][r].
// Deterministic fixed-order sum (no atomics).
// ---------------------------------------------------------------------------
__global__ __launch_bounds__(256) void reduce_g() {
    const int e = blockIdx.x * 256 + threadIdx.x;   // 0 .. 131071
    const int b = e >> 14;
    const int r = e & 16383;
    float sum = 0.0f;
#pragma unroll
    for (int sp = 0; sp < NSPLIT; sp++)
        sum += g_part[(((size_t)(b * NSPLIT + sp)) << 14) + r];
    g_full[e] = sum;
}

// ---------------------------------------------------------------------------
// Kernel 3: O_tile = Q_tile(128x128) @ G[b](128x128).
// Q is stored transposed in smem with stride 129 (conflict-free scalar loads),
// G row-major stride 128 (conflict-free float4 loads).
// ---------------------------------------------------------------------------
__global__ __launch_bounds__(256) void qg_kernel(const float* __restrict__ dec,
                                                 float* __restrict__ out) {
    extern __shared__ float s[];
    float* Qt = s;                    // [k][i], stride 129
    float* Gs = s + 128 * 129;        // [k][j], stride 128
    const int tid = threadIdx.x;
    const int b = blockIdx.y, qt = blockIdx.x;

    // Load Q tile transposed: global (i, k) -> smem [k][i].
    const float4* qsrc = (const float4*)(dec + ((size_t)(b * 16 + qt) << 14));
#pragma unroll
    for (int v = 0; v < 16; v++) {
        int idx = tid + v * 256;      // 0..4095 float4s
        int i  = idx >> 5;            // q-row
        int k4 = idx & 31;            // k/4
        float4 q = qsrc[idx];
        Qt[(k4 * 4 + 0) * 129 + i] = q.x;
        Qt[(k4 * 4 + 1) * 129 + i] = q.y;
        Qt[(k4 * 4 + 2) * 129 + i] = q.z;
        Qt[(k4 * 4 + 3) * 129 + i] = q.w;
    }
    // Load G[b].
    const float4* gsrc = (const float4*)(g_full + ((size_t)b << 14));
    float4* g4 = (float4*)Gs;
#pragma unroll
    for (int v = 0; v < 16; v++)
        g4[tid + v * 256] = gsrc[tid + v * 256];
    __syncthreads();

    const int tx = tid & 15, ty = tid >> 4;
    const int i0 = ty * 8, j0 = tx * 8;

    float acc[8][8];
#pragma unroll
    for (int ii = 0; ii < 8; ii++)
#pragma unroll
        for (int jj = 0; jj < 8; jj++) acc[ii][jj] = 0.0f;

#pragma unroll 4
    for (int k = 0; k < 128; k++) {
        float a[8], bv[8];
        const float* qrow = Qt + k * 129 + i0;
#pragma unroll
        for (int ii = 0; ii < 8; ii++) a[ii] = qrow[ii];
        const float* grow = Gs + k * 128 + j0;
        *(float4*)&bv[0] = *(const float4*)&grow[0];
        *(float4*)&bv[4] = *(const float4*)&grow[4];
#pragma unroll
        for (int ii = 0; ii < 8; ii++)
#pragma unroll
            for (int jj = 0; jj < 8; jj++)
                acc[ii][jj] = fmaf(a[ii], bv[jj], acc[ii][jj]);
    }

    float* obase = out + ((size_t)(b * 16 + qt) << 14);
#pragma unroll
    for (int ii = 0; ii < 8; ii++) {
        float* r = obase + (i0 + ii) * 128 + j0;
        *(float4*)&r[0] = make_float4(acc[ii][0], acc[ii][1], acc[ii][2], acc[ii][3]);
        *(float4*)&r[4] = make_float4(acc[ii][4], acc[ii][5], acc[ii][6], acc[ii][7]);
    }
}

// ---------------------------------------------------------------------------
// Launch
// ---------------------------------------------------------------------------
extern "C" void kernel_launch(void* const* d_in, const int* in_sizes, int n_in,
                              void* d_out, int out_size) {
    const float* enc = (const float*)d_in[0];   // encoder_hidden_states
    const float* dec = (const float*)d_in[1];   // decoder_hidden_states
    float* out = (float*)d_out;

    const int smem1 = 128 * 128 * 4;                       // 64 KB
    const int smem3 = (128 * 129 + 128 * 128) * 4;         // ~128.5 KB
    cudaFuncSetAttribute(ete_partial, cudaFuncAttributeMaxDynamicSharedMemorySize, smem1);
    cudaFuncSetAttribute(qg_kernel,   cudaFuncAttributeMaxDynamicSharedMemorySize, smem3);

    ete_partial<<<dim3(NSPLIT, BB), 256, smem1>>>(enc);
    reduce_g<<<(BB * DD * DD) / 256, 256>>>();
    qg_kernel<<<dim3(TT / 128, BB), 256, smem3>>>(dec, out);
}